// round 11
// baseline (speedup 1.0000x reference)
#include <cuda_runtime.h>
#include <cuda_bf16.h>
#include <cstdint>

#define B_ 64
#define T_ 1024
#define I_ 256
#define H_ 512
#define O_ 256
#define G_ 1536   // 3*H

// ======================= scratch (device globals) =======================
__device__ float g_gates[(size_t)T_ * G_ * B_];   // [t][g][b]
__device__ float g_out0[(size_t)T_ * H_ * B_];    // [t][h][b]
__device__ float g_out1[(size_t)T_ * H_ * B_];    // [t][h][b]
__device__ unsigned g_cnt[8 * 32];                 // per-group MONOTONIC counters (padded)
__device__ unsigned short g_hbh[2 * 64 * 512];     // h bf16-hi, parity double buffer, [b][k]
__device__ unsigned short g_hbl[2 * 64 * 512];     // h bf16-lo

// pre-swizzled bf16 operand tiles (GEMM phase)
__device__ __nv_bfloat16 g_w0h[12 * 4 * 8192], g_w0l[12 * 4 * 8192];
__device__ __nv_bfloat16 g_w1h[12 * 8 * 8192], g_w1l[12 * 8 * 8192];
__device__ __nv_bfloat16 g_wfh[ 2 * 8 * 8192], g_wfl[ 2 * 8 * 8192];
__device__ __nv_bfloat16 g_x0h[(size_t)T_ * 4 * 4096], g_x0l[(size_t)T_ * 4 * 4096];
__device__ __nv_bfloat16 g_x1h[(size_t)T_ * 8 * 4096], g_x1l[(size_t)T_ * 8 * 4096];

// ======================= small helpers =======================
__device__ __forceinline__ void cp_async16(void* smem_dst, const void* gsrc) {
    unsigned s = (unsigned)__cvta_generic_to_shared(smem_dst);
    asm volatile("cp.async.ca.shared.global [%0], [%1], 16;" :: "r"(s), "l"(gsrc));
}
__device__ __forceinline__ void cp_commit() {
    asm volatile("cp.async.commit_group;");
}
template <int N>
__device__ __forceinline__ void cp_wait() {
    asm volatile("cp.async.wait_group %0;" :: "n"(N));
}
__device__ __forceinline__ unsigned atom_add_release(unsigned* p, unsigned v) {
    unsigned old;
    asm volatile("atom.add.release.gpu.global.u32 %0, [%1], %2;"
                 : "=r"(old) : "l"(p), "r"(v) : "memory");
    return old;
}
__device__ __forceinline__ unsigned ld_acquire(const unsigned* p) {
    unsigned v;
    asm volatile("ld.acquire.gpu.global.u32 %0, [%1];" : "=r"(v) : "l"(p) : "memory");
    return v;
}
__device__ __forceinline__ uint32_t smem_u32(const void* p) {
    return (uint32_t)__cvta_generic_to_shared(p);
}
__host__ __device__ __forceinline__ uint32_t swz128(uint32_t o) {
    return o ^ ((o >> 3) & 0x70);
}
__device__ __forceinline__ unsigned short bf16hi_bits(float v, float& rem) {
    __nv_bfloat16 b = __float2bfloat16(v);
    rem = v - __bfloat162float(b);
    return *reinterpret_cast<unsigned short*>(&b);
}
__device__ __forceinline__ unsigned short bf16_bits(float v) {
    __nv_bfloat16 b = __float2bfloat16(v);
    return *reinterpret_cast<unsigned short*>(&b);
}

// ---- mma.sync / ldmatrix (base-target PTX) ----
__device__ __forceinline__ void ldsm_x4(unsigned* r, uint32_t addr) {
    asm volatile("ldmatrix.sync.aligned.m8n8.x4.shared.b16 {%0,%1,%2,%3}, [%4];"
        : "=r"(r[0]), "=r"(r[1]), "=r"(r[2]), "=r"(r[3]) : "r"(addr));
}
__device__ __forceinline__ void ldsm_x2(unsigned* r, uint32_t addr) {
    asm volatile("ldmatrix.sync.aligned.m8n8.x2.shared.b16 {%0,%1}, [%2];"
        : "=r"(r[0]), "=r"(r[1]) : "r"(addr));
}
__device__ __forceinline__ void mma_bf16(float* d, const unsigned* a, const unsigned* b) {
    asm volatile(
        "mma.sync.aligned.m16n8k16.row.col.f32.bf16.bf16.f32 "
        "{%0,%1,%2,%3}, {%4,%5,%6,%7}, {%8,%9}, {%0,%1,%2,%3};"
        : "+f"(d[0]), "+f"(d[1]), "+f"(d[2]), "+f"(d[3])
        : "r"(a[0]), "r"(a[1]), "r"(a[2]), "r"(a[3]), "r"(b[0]), "r"(b[1]));
}

// =========================================================================
// Zero barrier counters (before each recurrent launch; graph-replay safe)
// =========================================================================
__global__ void k_zero() {
    g_cnt[threadIdx.x] = 0u;
}

// =========================================================================
// Prep: W [M,K] fp32 -> hi/lo bf16 SW128 tiles [mi][s][128x64]
// =========================================================================
__global__ __launch_bounds__(256) void k_prep_w(
    const float* __restrict__ src, __nv_bfloat16* __restrict__ dh,
    __nv_bfloat16* __restrict__ dl, int K)
{
    int mi = blockIdx.x, s = blockIdx.y, nS = gridDim.y;
    size_t tbase = ((size_t)mi * nS + s) * 16384;
#pragma unroll
    for (int i = 0; i < 8; i++) {
        int it  = threadIdx.x + i * 256;
        int row = it >> 4;
        int q   = it & 15;
        float4 v = *(const float4*)(src + (size_t)(mi * 128 + row) * K + s * 64 + q * 4);
        float r0, r1, r2, r3;
        ushort4 hi, lo;
        hi.x = bf16hi_bits(v.x, r0); hi.y = bf16hi_bits(v.y, r1);
        hi.z = bf16hi_bits(v.z, r2); hi.w = bf16hi_bits(v.w, r3);
        lo.x = bf16_bits(r0); lo.y = bf16_bits(r1);
        lo.z = bf16_bits(r2); lo.w = bf16_bits(r3);
        uint32_t sw = swz128((uint32_t)(row * 128 + q * 8));
        *(ushort4*)((char*)dh + tbase + sw) = hi;
        *(ushort4*)((char*)dl + tbase + sw) = lo;
    }
}

// =========================================================================
// Prep: x[b][t][k] fp32 -> hi/lo bf16 SW128 tiles [t][s][64(b)x64(k)]
// =========================================================================
__global__ __launch_bounds__(256) void k_prep_x(const float* __restrict__ x) {
    int t = blockIdx.x, s = blockIdx.y, nS = gridDim.y;
    size_t tbase = ((size_t)t * nS + s) * 8192;
#pragma unroll
    for (int i = 0; i < 4; i++) {
        int it = threadIdx.x + i * 256;
        int b  = it >> 4;
        int q  = it & 15;
        float4 v = *(const float4*)(x + ((size_t)b * T_ + t) * I_ + s * 64 + q * 4);
        float r0, r1, r2, r3;
        ushort4 hi, lo;
        hi.x = bf16hi_bits(v.x, r0); hi.y = bf16hi_bits(v.y, r1);
        hi.z = bf16hi_bits(v.z, r2); hi.w = bf16hi_bits(v.w, r3);
        lo.x = bf16_bits(r0); lo.y = bf16_bits(r1);
        lo.z = bf16_bits(r2); lo.w = bf16_bits(r3);
        uint32_t sw = swz128((uint32_t)(b * 128 + q * 8));
        *(ushort4*)((char*)g_x0h + tbase + sw) = hi;
        *(ushort4*)((char*)g_x0l + tbase + sw) = lo;
    }
}

// =========================================================================
// Prep: out[t][h][b] fp32 -> hi/lo bf16 SW128 tiles [t][s][64(b)x64(k)]
// =========================================================================
__global__ __launch_bounds__(256) void k_prep_h(
    const float* __restrict__ src, __nv_bfloat16* __restrict__ dh,
    __nv_bfloat16* __restrict__ dl)
{
    __shared__ float sm[64 * 65];
    int t = blockIdx.x, s = blockIdx.y, nS = gridDim.y;
    size_t tbase = ((size_t)t * nS + s) * 8192;
    const float* blk = src + ((size_t)t * H_ + s * 64) * B_;
#pragma unroll
    for (int i = 0; i < 16; i++) {
        int idx = threadIdx.x + i * 256;
        int k = idx >> 6, b = idx & 63;
        sm[k * 65 + b] = blk[idx];
    }
    __syncthreads();
#pragma unroll
    for (int i = 0; i < 4; i++) {
        int it = threadIdx.x + i * 256;
        int b  = it >> 4;
        int q  = it & 15;
        float v0 = sm[(q * 4 + 0) * 65 + b];
        float v1 = sm[(q * 4 + 1) * 65 + b];
        float v2 = sm[(q * 4 + 2) * 65 + b];
        float v3 = sm[(q * 4 + 3) * 65 + b];
        float r0, r1, r2, r3;
        ushort4 hi, lo;
        hi.x = bf16hi_bits(v0, r0); hi.y = bf16hi_bits(v1, r1);
        hi.z = bf16hi_bits(v2, r2); hi.w = bf16hi_bits(v3, r3);
        lo.x = bf16_bits(r0); lo.y = bf16_bits(r1);
        lo.z = bf16_bits(r2); lo.w = bf16_bits(r3);
        uint32_t sw = swz128((uint32_t)(b * 128 + q * 8));
        *(ushort4*)((char*)dh + tbase + sw) = hi;
        *(ushort4*)((char*)dl + tbase + sw) = lo;
    }
}

// =========================================================================
// mma.sync GEMM (unchanged, validated)
// =========================================================================
#define TCB_BYTES 65536
#define TC_SMEM_TOTAL (1024 + 2 * TCB_BYTES)

__global__ __launch_bounds__(256) void k_gemm_mma(
    const __nv_bfloat16* __restrict__ Wh, const __nv_bfloat16* __restrict__ Wl,
    const __nv_bfloat16* __restrict__ Xh, const __nv_bfloat16* __restrict__ Xl,
    const float* __restrict__ bias, float* __restrict__ C,
    int nS, int M, int mode)
{
    extern __shared__ __align__(16) char smem[];
    uint32_t sb = smem_u32(smem);
    int tid  = threadIdx.x;
    int wid  = tid >> 5;
    int lane = tid & 31;
    int mi   = blockIdx.x;
    int m0   = mi * 128;
    int t0   = blockIdx.y * 2;

    int wm = (wid >> 1) * 32;
    int wn = (wid & 1);

    uint32_t pA = (uint32_t)((wm + (lane & 15)) * 128 + (lane >> 4) * 16);
    uint32_t rowB = (uint32_t)((lane & 7) + ((lane >> 4) & 1) * 8);
    uint32_t koffB = (uint32_t)(((lane >> 3) & 1) * 16);

    float acc[2][8][4];
#pragma unroll
    for (int i = 0; i < 2; i++)
#pragma unroll
        for (int n = 0; n < 8; n++)
#pragma unroll
            for (int c = 0; c < 4; c++) acc[i][n][c] = 0.f;

    auto issue_slab = [&](int s, int bi) {
        char* dst = smem + 1024 + bi * TCB_BYTES;
        const char* wh  = (const char*)Wh + ((size_t)mi * nS + s) * 16384;
        const char* wl  = (const char*)Wl + ((size_t)mi * nS + s) * 16384;
        const char* x0h = (const char*)Xh + ((size_t)t0 * nS + s) * 8192;
        const char* x1h = (const char*)Xh + ((size_t)(t0 + 1) * nS + s) * 8192;
        const char* x0l = (const char*)Xl + ((size_t)t0 * nS + s) * 8192;
        const char* x1l = (const char*)Xl + ((size_t)(t0 + 1) * nS + s) * 8192;
#pragma unroll
        for (int i = 0; i < 16; i++) {
            int c   = tid + i * 256;
            int reg = c >> 10;
            int off = (c & 1023) * 16;
            const char* src;
            if      (reg == 0) src = wh + off;
            else if (reg == 1) src = wl + off;
            else if (reg == 2) src = (off < 8192) ? x0h + off : x1h + (off - 8192);
            else               src = (off < 8192) ? x0l + off : x1l + (off - 8192);
            cp_async16(dst + reg * 16384 + off, src);
        }
        cp_commit();
    };

    issue_slab(0, 0);

    for (int s = 0; s < nS; s++) {
        int bi = s & 1;
        if (s + 1 < nS) {
            issue_slab(s + 1, (s + 1) & 1);
            cp_wait<1>();
        } else {
            cp_wait<0>();
        }
        __syncthreads();

        uint32_t bufb = sb + 1024 + (uint32_t)bi * TCB_BYTES;
        uint32_t aH = bufb;
        uint32_t aL = bufb + 16384;
        uint32_t bH = bufb + 32768 + (uint32_t)wn * 8192;
        uint32_t bL = bufb + 49152 + (uint32_t)wn * 8192;

#pragma unroll
        for (int ks = 0; ks < 4; ks++) {
            unsigned ah[2][4], al[2][4];
            ldsm_x4(ah[0], aH + swz128(pA + ks * 32));
            ldsm_x4(ah[1], aH + swz128(pA + 2048 + ks * 32));
            ldsm_x4(al[0], aL + swz128(pA + ks * 32));
            ldsm_x4(al[1], aL + swz128(pA + 2048 + ks * 32));
#pragma unroll
            for (int half = 0; half < 2; half++) {
                unsigned bh2[2][4], bl2[2][4];
#pragma unroll
                for (int np2 = 0; np2 < 2; np2++) {
                    int np = half * 2 + np2;
                    uint32_t pB = (uint32_t)((np * 16 + rowB) * 128) + koffB;
                    ldsm_x4(bh2[np2], bH + swz128(pB + ks * 32));
                    ldsm_x4(bl2[np2], bL + swz128(pB + ks * 32));
                }
#pragma unroll
                for (int np2 = 0; np2 < 2; np2++) {
#pragma unroll
                    for (int e = 0; e < 2; e++) {
                        int nt = half * 4 + np2 * 2 + e;
                        const unsigned* bfh = &bh2[np2][e * 2];
                        const unsigned* bfl = &bl2[np2][e * 2];
#pragma unroll
                        for (int i = 0; i < 2; i++) {
                            mma_bf16(acc[i][nt], ah[i], bfh);
                            mma_bf16(acc[i][nt], ah[i], bfl);
                            mma_bf16(acc[i][nt], al[i], bfh);
                        }
                    }
                }
            }
        }
        __syncthreads();
    }

    int qrow = lane >> 2;
    int qcol = (lane & 3) * 2;

    if (mode == 0) {
        int t = t0 + wn;
#pragma unroll
        for (int i = 0; i < 2; i++) {
            int r0 = wm + i * 16 + qrow;
            int r1 = r0 + 8;
            float bb0 = bias[m0 + r0];
            float bb1 = bias[m0 + r1];
            float* d0 = C + ((size_t)t * M + m0 + r0) * B_;
            float* d1 = C + ((size_t)t * M + m0 + r1) * B_;
#pragma unroll
            for (int nt = 0; nt < 8; nt++) {
                int col = nt * 8 + qcol;
                *(float2*)(d0 + col) = make_float2(acc[i][nt][0] + bb0, acc[i][nt][1] + bb0);
                *(float2*)(d1 + col) = make_float2(acc[i][nt][2] + bb1, acc[i][nt][3] + bb1);
            }
        }
    } else {
        float* stage = (float*)(smem + 1024);
#pragma unroll
        for (int i = 0; i < 2; i++) {
            int r0 = wm + i * 16 + qrow;
            int r1 = r0 + 8;
            float bb0 = bias[m0 + r0];
            float bb1 = bias[m0 + r1];
#pragma unroll
            for (int nt = 0; nt < 8; nt++) {
                int col = wn * 64 + nt * 8 + qcol;
                stage[r0 * 132 + col]     = acc[i][nt][0] + bb0;
                stage[r0 * 132 + col + 1] = acc[i][nt][1] + bb0;
                stage[r1 * 132 + col]     = acc[i][nt][2] + bb1;
                stage[r1 * 132 + col + 1] = acc[i][nt][3] + bb1;
            }
        }
        __syncthreads();
        int n    = tid >> 1;
        int half = tid & 1;
        int tt   = t0 + (n >> 6);
        int b2   = n & 63;
        float* dst = C + ((size_t)b2 * T_ + tt) * M + m0 + half * 64;
#pragma unroll
        for (int q = 0; q < 16; q++) {
            float4 v = make_float4(stage[(half * 64 + q * 4 + 0) * 132 + n],
                                   stage[(half * 64 + q * 4 + 1) * 132 + n],
                                   stage[(half * 64 + q * 4 + 2) * 132 + n],
                                   stage[(half * 64 + q * 4 + 3) * 132 + n]);
            *(float4*)(dst + q * 4) = v;
        }
    }
}

// =========================================================================
// Persistent GRU layer, tensor-core matvec, TWO batch groups per CTA
// (software-pipelined to hide barrier+exchange latency).
// 64 CTAs = 4 group-pairs x 16 j-subs. CTA serves groups gpair and gpair+4.
// W slice shared between groups (same j's). One shared smem h buffer,
// reloaded per half-iteration. Monotonic counters: atom.add.release +
// ld.acquire >= 16*t.
// SMEM: Wh/Wl bf16 [96][1040B] + h hi/lo [8][1040B] + hg [96][12] fp32.
// =========================================================================
#define OFF_WL 99840
#define OFF_HH 199680
#define OFF_HL 208000
#define OFF_HG 216320
#define GRU9_SMEM_BYTES 220928

__global__ __launch_bounds__(256) void k_gru9(
    const float* __restrict__ gates,   // [t][g][b], includes b_ih
    const float* __restrict__ Whh,     // [3H][H]
    const float* __restrict__ bhh,     // [3H]
    float* __restrict__ out,           // [t][h][b]
    unsigned short* __restrict__ hbh,  // [2][64][512] bf16-hi bits
    unsigned short* __restrict__ hbl)  // [2][64][512] bf16-lo bits
{
    extern __shared__ __align__(16) char smem[];
    uint32_t sb = smem_u32(smem);

    int tid   = threadIdx.x;
    int w     = tid >> 5;
    int lane  = tid & 31;
    int gpair = blockIdx.x >> 4;    // 0..3
    int sub   = blockIdx.x & 15;    // 0..15
    int jj    = tid >> 3;           // 0..31
    int bl    = tid & 7;            // 0..7
    int j0    = sub * 32;
    int j     = j0 + jj;
    int gA    = gpair;
    int gB    = gpair + 4;
    int bgA   = gA * 8;
    int bgB   = gB * 8;
    int bA    = bgA + bl;
    int bB    = bgB + bl;
    unsigned* cA = &g_cnt[gA * 32];
    unsigned* cB = &g_cnt[gB * 32];

    // ---- init: Whh slice -> bf16 hi/lo smem, row = jj*3+gate ----
    for (int idx = tid; idx < 96 * 512; idx += 256) {
        int r = idx >> 9;           // 0..95
        int k = idx & 511;
        int gg = r % 3;
        int ww = r / 3;
        float v = Whh[((size_t)(gg * H_ + j0 + ww)) * H_ + k];
        float rem;
        unsigned short hi = bf16hi_bits(v, rem);
        unsigned short lo = bf16_bits(rem);
        *(unsigned short*)(smem + r * 1040 + k * 2)          = hi;
        *(unsigned short*)(smem + OFF_WL + r * 1040 + k * 2) = lo;
    }
    // zero h smem (hh + hl) — used for t=0 by both groups
    for (int idx = tid; idx < (2 * 8320) / 4; idx += 256)
        *(uint32_t*)(smem + OFF_HH + idx * 4) = 0u;

    float bhr = bhh[j];
    float bhz = bhh[H_ + j];
    float bhn = bhh[2 * H_ + j];
    float holdA = 0.f, holdB = 0.f;

    const float* gpA = gates + (size_t)j * B_ + bA;
    const float* gpB = gates + (size_t)j * B_ + bB;
    const size_t tstride = (size_t)G_ * B_;
    const size_t goff    = (size_t)H_ * B_;
    float xrA = __ldcs(gpA), xzA = __ldcs(gpA + goff), xnA = __ldcs(gpA + 2 * goff);
    float xrB = __ldcs(gpB), xzB = __ldcs(gpB + goff), xnB = __ldcs(gpB + 2 * goff);

    // ldmatrix address patterns (byte offsets, k-chunk added in loop)
    uint32_t paH = sb + (uint32_t)((w * 16 + (lane & 15)) * 1040 + (lane >> 4) * 16);
    uint32_t paL = paH + OFF_WL;
    uint32_t pbH = sb + OFF_HH + (uint32_t)((lane & 7) * 1040 + ((lane >> 3) & 1) * 16);
    uint32_t pbL = pbH + (OFF_HL - OFF_HH);
    float* hg = (float*)(smem + OFF_HG);

    __syncthreads();

    for (int t = 0; t < T_; t++) {
        int par = t & 1;
        unsigned tgt = 16u * (unsigned)t;

#pragma unroll
        for (int half = 0; half < 2; half++) {
            unsigned* cnt = half ? cB : cA;
            int bg0 = half ? bgB : bgA;

            // ---- wait peers' h(t-1), reload into shared smem h buffer ----
            if (t > 0) {
                if (tid == 0) {
                    while (ld_acquire(cnt) < tgt) { }
                }
                __syncthreads();
                int row  = tid >> 5;            // 0..7 (local b)
                int colb = lane * 32;           // byte offset in 1024B row
                int ppar = (t - 1) & 1;
                const char* srch = (const char*)(hbh + ppar * 32768 + (bg0 + row) * 512) + colb;
                const char* srcl = (const char*)(hbl + ppar * 32768 + (bg0 + row) * 512) + colb;
                float4 v0 = __ldcg((const float4*)srch);
                float4 v1 = __ldcg((const float4*)(srch + 16));
                float4 u0 = __ldcg((const float4*)srcl);
                float4 u1 = __ldcg((const float4*)(srcl + 16));
                *(float4*)(smem + OFF_HH + row * 1040 + colb)      = v0;
                *(float4*)(smem + OFF_HH + row * 1040 + colb + 16) = v1;
                *(float4*)(smem + OFF_HL + row * 1040 + colb)      = u0;
                *(float4*)(smem + OFF_HL + row * 1040 + colb + 16) = u1;
                __syncthreads();
            }

            // ---- tensor-core hg = Ws @ h (warps 0-5) ----
            if (w < 6) {
                float acc[4] = {0.f, 0.f, 0.f, 0.f};
#pragma unroll
                for (int ks = 0; ks < 32; ks++) {
                    uint32_t ko = (uint32_t)ks * 32;
                    unsigned ah[4], al[4], bh2[2], bl2[2];
                    ldsm_x4(ah, paH + ko);
                    ldsm_x4(al, paL + ko);
                    ldsm_x2(bh2, pbH + ko);
                    ldsm_x2(bl2, pbL + ko);
                    mma_bf16(acc, ah, bh2);
                    mma_bf16(acc, ah, bl2);
                    mma_bf16(acc, al, bh2);
                }
                int r0 = w * 16 + (lane >> 2);
                *(float2*)&hg[r0 * 12 + (lane & 3) * 2]       = make_float2(acc[0], acc[1]);
                *(float2*)&hg[(r0 + 8) * 12 + (lane & 3) * 2] = make_float2(acc[2], acc[3]);
            }
            __syncthreads();

            // ---- gate math (all 256 threads, one (j,b) each) ----
            float ar = hg[(jj * 3 + 0) * 12 + bl];
            float az = hg[(jj * 3 + 1) * 12 + bl];
            float an = hg[(jj * 3 + 2) * 12 + bl];

            float xr = half ? xrB : xrA;
            float xz = half ? xzB : xzA;
            float xn = half ? xnB : xnA;
            float hold = half ? holdB : holdA;

            float r = 1.f / (1.f + expf(-(xr + ar + bhr)));
            float z = 1.f / (1.f + expf(-(xz + az + bhz)));
            float n = tanhf(xn + r * (an + bhn));
            float hnew = (1.f - z) * n + z * hold;
            if (half) holdB = hnew; else holdA = hnew;

            int b = half ? bB : bA;
            out[((size_t)t * H_ + j) * B_ + b] = hnew;
            {
                float rem;
                unsigned short hi = bf16hi_bits(hnew, rem);
                unsigned short lo = bf16_bits(rem);
                hbh[par * 32768 + b * 512 + j] = hi;
                hbl[par * 32768 + b * 512 + j] = lo;
            }

            // prefetch next-step gates for this group (independent of h)
            if (t + 1 < T_) {
                const float* gq = (half ? gpB : gpA) + (size_t)(t + 1) * tstride;
                float pxr = __ldcs(gq);
                float pxz = __ldcs(gq + goff);
                float pxn = __ldcs(gq + 2 * goff);
                if (half) { xrB = pxr; xzB = pxz; xnB = pxn; }
                else      { xrA = pxr; xzA = pxz; xnA = pxn; }
            }

            // ---- arrive: publish h(t) for this group ----
            __syncthreads();
            if (tid == 0) atom_add_release(cnt, 1u);
        }
    }
}

// =========================================================================
// hidden[l][b][h] = out_l[T-1][h][b]
// =========================================================================
__global__ __launch_bounds__(256) void k_hidden(float* __restrict__ dst) {
    int idx = blockIdx.x * 256 + threadIdx.x;
    int l  = idx >> 15;
    int rem = idx & 32767;
    int bb = rem >> 9;
    int h  = rem & 511;
    const float* src = l ? g_out1 : g_out0;
    dst[idx] = src[((size_t)(T_ - 1) * H_ + h) * B_ + bb];
}

// =========================================================================
extern "C" void kernel_launch(void* const* d_in, const int* in_sizes, int n_in,
                              void* d_out, int out_size) {
    const float* x    = (const float*)d_in[0];
    const float* Wih0 = (const float*)d_in[1];
    const float* Whh0 = (const float*)d_in[2];
    const float* bih0 = (const float*)d_in[3];
    const float* bhh0 = (const float*)d_in[4];
    const float* Wih1 = (const float*)d_in[5];
    const float* Whh1 = (const float*)d_in[6];
    const float* bih1 = (const float*)d_in[7];
    const float* bhh1 = (const float*)d_in[8];
    const float* fcw  = (const float*)d_in[9];
    const float* fcb  = (const float*)d_in[10];
    float* out = (float*)d_out;

    (void)in_sizes; (void)n_in; (void)out_size;

    cudaFuncSetAttribute(k_gru9, cudaFuncAttributeMaxDynamicSharedMemorySize,
                         GRU9_SMEM_BYTES);
    cudaFuncSetAttribute(k_gemm_mma, cudaFuncAttributeMaxDynamicSharedMemorySize,
                         TC_SMEM_TOTAL);

    float *p_gates, *p_out0, *p_out1;
    cudaGetSymbolAddress((void**)&p_gates, g_gates);
    cudaGetSymbolAddress((void**)&p_out0,  g_out0);
    cudaGetSymbolAddress((void**)&p_out1,  g_out1);
    unsigned short *hbh, *hbl;
    cudaGetSymbolAddress((void**)&hbh, g_hbh);
    cudaGetSymbolAddress((void**)&hbl, g_hbl);
    __nv_bfloat16 *w0h, *w0l, *w1h, *w1l, *wfh, *wfl, *x0h, *x0l, *x1h, *x1l;
    cudaGetSymbolAddress((void**)&w0h, g_w0h);
    cudaGetSymbolAddress((void**)&w0l, g_w0l);
    cudaGetSymbolAddress((void**)&w1h, g_w1h);
    cudaGetSymbolAddress((void**)&w1l, g_w1l);
    cudaGetSymbolAddress((void**)&wfh, g_wfh);
    cudaGetSymbolAddress((void**)&wfl, g_wfl);
    cudaGetSymbolAddress((void**)&x0h, g_x0h);
    cudaGetSymbolAddress((void**)&x0l, g_x0l);
    cudaGetSymbolAddress((void**)&x1h, g_x1h);
    cudaGetSymbolAddress((void**)&x1l, g_x1l);

    // operand prep
    k_prep_w<<<dim3(12, 4), 256>>>(Wih0, w0h, w0l, I_);
    k_prep_w<<<dim3(12, 8), 256>>>(Wih1, w1h, w1l, H_);
    k_prep_w<<<dim3(2, 8),  256>>>(fcw,  wfh, wfl, H_);
    k_prep_x<<<dim3(1024, 4), 256>>>(x);

    // layer 0
    k_gemm_mma<<<dim3(12, 512), 256, TC_SMEM_TOTAL>>>(w0h, w0l, x0h, x0l, bih0, p_gates, 4, G_, 0);
    k_zero<<<1, 256>>>();
    k_gru9<<<64, 256, GRU9_SMEM_BYTES>>>(p_gates, Whh0, bhh0, p_out0, hbh, hbl);

    // layer 1
    k_prep_h<<<dim3(1024, 8), 256>>>(p_out0, x1h, x1l);
    k_gemm_mma<<<dim3(12, 512), 256, TC_SMEM_TOTAL>>>(w1h, w1l, x1h, x1l, bih1, p_gates, 8, G_, 0);
    k_zero<<<1, 256>>>();
    k_gru9<<<64, 256, GRU9_SMEM_BYTES>>>(p_gates, Whh1, bhh1, p_out1, hbh, hbl);

    // FC
    k_prep_h<<<dim3(1024, 8), 256>>>(p_out1, x1h, x1l);
    k_gemm_mma<<<dim3(2, 512), 256, TC_SMEM_TOTAL>>>(wfh, wfl, x1h, x1l, fcb, out, 8, O_, 1);

    k_hidden<<<256, 256>>>(out + (size_t)B_ * T_ * O_);
}

// round 12
// speedup vs baseline: 1.3743x; 1.3743x over previous
#include <cuda_runtime.h>
#include <cuda_bf16.h>
#include <cstdint>

#define B_ 64
#define T_ 1024
#define I_ 256
#define H_ 512
#define O_ 256
#define G_ 1536   // 3*H

// ======================= scratch (device globals) =======================
__device__ float g_gates[(size_t)T_ * G_ * B_];   // [t][g][b]
__device__ float g_out0[(size_t)T_ * H_ * B_];    // [t][h][b]
__device__ float g_out1[(size_t)T_ * H_ * B_];    // [t][h][b]
__device__ unsigned g_cnt[8 * 32];                 // per-group barrier counters (padded)
__device__ unsigned g_gen2[8 * 32];                // per-group generations (padded)
__device__ unsigned short g_hbh[2 * 64 * 512];     // h bf16-hi, parity double buffer, [b][k]
__device__ unsigned short g_hbl[2 * 64 * 512];     // h bf16-lo

// pre-swizzled bf16 operand tiles (GEMM phase)
__device__ __nv_bfloat16 g_w0h[12 * 4 * 8192], g_w0l[12 * 4 * 8192];
__device__ __nv_bfloat16 g_w1h[12 * 8 * 8192], g_w1l[12 * 8 * 8192];
__device__ __nv_bfloat16 g_wfh[ 2 * 8 * 8192], g_wfl[ 2 * 8 * 8192];
__device__ __nv_bfloat16 g_x0h[(size_t)T_ * 4 * 4096], g_x0l[(size_t)T_ * 4 * 4096];
__device__ __nv_bfloat16 g_x1h[(size_t)T_ * 8 * 4096], g_x1l[(size_t)T_ * 8 * 4096];

// ======================= small helpers =======================
__device__ __forceinline__ void cp_async16(void* smem_dst, const void* gsrc) {
    unsigned s = (unsigned)__cvta_generic_to_shared(smem_dst);
    asm volatile("cp.async.ca.shared.global [%0], [%1], 16;" :: "r"(s), "l"(gsrc));
}
__device__ __forceinline__ void cp_commit() {
    asm volatile("cp.async.commit_group;");
}
template <int N>
__device__ __forceinline__ void cp_wait() {
    asm volatile("cp.async.wait_group %0;" :: "n"(N));
}
__device__ __forceinline__ unsigned atom_add_release(unsigned* p, unsigned v) {
    unsigned old;
    asm volatile("atom.add.release.gpu.global.u32 %0, [%1], %2;"
                 : "=r"(old) : "l"(p), "r"(v) : "memory");
    return old;
}
__device__ __forceinline__ unsigned ld_acquire(const unsigned* p) {
    unsigned v;
    asm volatile("ld.acquire.gpu.global.u32 %0, [%1];" : "=r"(v) : "l"(p) : "memory");
    return v;
}
__device__ __forceinline__ void st_release(unsigned* p, unsigned v) {
    asm volatile("st.release.gpu.global.u32 [%0], %1;" :: "l"(p), "r"(v) : "memory");
}
__device__ __forceinline__ uint32_t smem_u32(const void* p) {
    return (uint32_t)__cvta_generic_to_shared(p);
}
__host__ __device__ __forceinline__ uint32_t swz128(uint32_t o) {
    return o ^ ((o >> 3) & 0x70);
}
__device__ __forceinline__ unsigned short bf16hi_bits(float v, float& rem) {
    __nv_bfloat16 b = __float2bfloat16(v);
    rem = v - __bfloat162float(b);
    return *reinterpret_cast<unsigned short*>(&b);
}
__device__ __forceinline__ unsigned short bf16_bits(float v) {
    __nv_bfloat16 b = __float2bfloat16(v);
    return *reinterpret_cast<unsigned short*>(&b);
}

// ---- mma.sync / ldmatrix (base-target PTX) ----
__device__ __forceinline__ void ldsm_x4(unsigned* r, uint32_t addr) {
    asm volatile("ldmatrix.sync.aligned.m8n8.x4.shared.b16 {%0,%1,%2,%3}, [%4];"
        : "=r"(r[0]), "=r"(r[1]), "=r"(r[2]), "=r"(r[3]) : "r"(addr));
}
__device__ __forceinline__ void ldsm_x2(unsigned* r, uint32_t addr) {
    asm volatile("ldmatrix.sync.aligned.m8n8.x2.shared.b16 {%0,%1}, [%2];"
        : "=r"(r[0]), "=r"(r[1]) : "r"(addr));
}
__device__ __forceinline__ void mma_bf16(float* d, const unsigned* a, const unsigned* b) {
    asm volatile(
        "mma.sync.aligned.m16n8k16.row.col.f32.bf16.bf16.f32 "
        "{%0,%1,%2,%3}, {%4,%5,%6,%7}, {%8,%9}, {%0,%1,%2,%3};"
        : "+f"(d[0]), "+f"(d[1]), "+f"(d[2]), "+f"(d[3])
        : "r"(a[0]), "r"(a[1]), "r"(a[2]), "r"(a[3]), "r"(b[0]), "r"(b[1]));
}

// =========================================================================
// Prep: W [M,K] fp32 -> hi/lo bf16 SW128 tiles [mi][s][128x64]
// =========================================================================
__global__ __launch_bounds__(256) void k_prep_w(
    const float* __restrict__ src, __nv_bfloat16* __restrict__ dh,
    __nv_bfloat16* __restrict__ dl, int K)
{
    int mi = blockIdx.x, s = blockIdx.y, nS = gridDim.y;
    size_t tbase = ((size_t)mi * nS + s) * 16384;
#pragma unroll
    for (int i = 0; i < 8; i++) {
        int it  = threadIdx.x + i * 256;
        int row = it >> 4;
        int q   = it & 15;
        float4 v = *(const float4*)(src + (size_t)(mi * 128 + row) * K + s * 64 + q * 4);
        float r0, r1, r2, r3;
        ushort4 hi, lo;
        hi.x = bf16hi_bits(v.x, r0); hi.y = bf16hi_bits(v.y, r1);
        hi.z = bf16hi_bits(v.z, r2); hi.w = bf16hi_bits(v.w, r3);
        lo.x = bf16_bits(r0); lo.y = bf16_bits(r1);
        lo.z = bf16_bits(r2); lo.w = bf16_bits(r3);
        uint32_t sw = swz128((uint32_t)(row * 128 + q * 8));
        *(ushort4*)((char*)dh + tbase + sw) = hi;
        *(ushort4*)((char*)dl + tbase + sw) = lo;
    }
}

// =========================================================================
// Prep: x[b][t][k] fp32 -> hi/lo bf16 SW128 tiles [t][s][64(b)x64(k)]
// =========================================================================
__global__ __launch_bounds__(256) void k_prep_x(const float* __restrict__ x) {
    int t = blockIdx.x, s = blockIdx.y, nS = gridDim.y;
    size_t tbase = ((size_t)t * nS + s) * 8192;
#pragma unroll
    for (int i = 0; i < 4; i++) {
        int it = threadIdx.x + i * 256;
        int b  = it >> 4;
        int q  = it & 15;
        float4 v = *(const float4*)(x + ((size_t)b * T_ + t) * I_ + s * 64 + q * 4);
        float r0, r1, r2, r3;
        ushort4 hi, lo;
        hi.x = bf16hi_bits(v.x, r0); hi.y = bf16hi_bits(v.y, r1);
        hi.z = bf16hi_bits(v.z, r2); hi.w = bf16hi_bits(v.w, r3);
        lo.x = bf16_bits(r0); lo.y = bf16_bits(r1);
        lo.z = bf16_bits(r2); lo.w = bf16_bits(r3);
        uint32_t sw = swz128((uint32_t)(b * 128 + q * 8));
        *(ushort4*)((char*)g_x0h + tbase + sw) = hi;
        *(ushort4*)((char*)g_x0l + tbase + sw) = lo;
    }
}

// =========================================================================
// Prep: out[t][h][b] fp32 -> hi/lo bf16 SW128 tiles [t][s][64(b)x64(k)]
// =========================================================================
__global__ __launch_bounds__(256) void k_prep_h(
    const float* __restrict__ src, __nv_bfloat16* __restrict__ dh,
    __nv_bfloat16* __restrict__ dl)
{
    __shared__ float sm[64 * 65];
    int t = blockIdx.x, s = blockIdx.y, nS = gridDim.y;
    size_t tbase = ((size_t)t * nS + s) * 8192;
    const float* blk = src + ((size_t)t * H_ + s * 64) * B_;
#pragma unroll
    for (int i = 0; i < 16; i++) {
        int idx = threadIdx.x + i * 256;
        int k = idx >> 6, b = idx & 63;
        sm[k * 65 + b] = blk[idx];
    }
    __syncthreads();
#pragma unroll
    for (int i = 0; i < 4; i++) {
        int it = threadIdx.x + i * 256;
        int b  = it >> 4;
        int q  = it & 15;
        float v0 = sm[(q * 4 + 0) * 65 + b];
        float v1 = sm[(q * 4 + 1) * 65 + b];
        float v2 = sm[(q * 4 + 2) * 65 + b];
        float v3 = sm[(q * 4 + 3) * 65 + b];
        float r0, r1, r2, r3;
        ushort4 hi, lo;
        hi.x = bf16hi_bits(v0, r0); hi.y = bf16hi_bits(v1, r1);
        hi.z = bf16hi_bits(v2, r2); hi.w = bf16hi_bits(v3, r3);
        lo.x = bf16_bits(r0); lo.y = bf16_bits(r1);
        lo.z = bf16_bits(r2); lo.w = bf16_bits(r3);
        uint32_t sw = swz128((uint32_t)(b * 128 + q * 8));
        *(ushort4*)((char*)dh + tbase + sw) = hi;
        *(ushort4*)((char*)dl + tbase + sw) = lo;
    }
}

// =========================================================================
// mma.sync GEMM, M=64 tiles, 2 CTAs/SM.
// C_t[M][64] = W[M,K] @ X_t[K,64] + bias, two t per CTA (N=128).
// Slab (64 K): Ah 8K | Al 8K | Bh 16K | Bl 16K = 48KB, double-buffered.
// 8 warps: 4 m16-tiles x 2 t-halves; warp = 16M x 64N.
// W prep tiles are 128-row; sub-tile = +(mi&1)*8192 bytes (row-swizzle safe).
//   mode 0: C[t][m][b]   mode 1: C[(b*T+t)*M + m]
// =========================================================================
#define TCB_BYTES 49152
#define TC_SMEM_TOTAL (1024 + 2 * TCB_BYTES)

__global__ __launch_bounds__(256, 2) void k_gemm_mma(
    const __nv_bfloat16* __restrict__ Wh, const __nv_bfloat16* __restrict__ Wl,
    const __nv_bfloat16* __restrict__ Xh, const __nv_bfloat16* __restrict__ Xl,
    const float* __restrict__ bias, float* __restrict__ C,
    int nS, int M, int mode)
{
    extern __shared__ __align__(16) char smem[];
    uint32_t sb = smem_u32(smem);
    int tid  = threadIdx.x;
    int wid  = tid >> 5;
    int lane = tid & 31;
    int mi   = blockIdx.x;          // 64-row tile index
    int m0   = mi * 64;
    int t0   = blockIdx.y * 2;

    int wm = (wid >> 1) * 16;       // warp m-base within 64 (0,16,32,48)
    int wn = (wid & 1);             // timestep select

    uint32_t pA = (uint32_t)((wm + (lane & 15)) * 128 + (lane >> 4) * 16);
    uint32_t rowB = (uint32_t)((lane & 7) + ((lane >> 4) & 1) * 8);
    uint32_t koffB = (uint32_t)(((lane >> 3) & 1) * 16);

    float acc[8][4];
#pragma unroll
    for (int n = 0; n < 8; n++)
#pragma unroll
        for (int c = 0; c < 4; c++) acc[n][c] = 0.f;

    // W source: 128-row tiles; our 64-row half is at +(mi&1)*8192
    auto issue_slab = [&](int s, int bi) {
        char* dst = smem + 1024 + bi * TCB_BYTES;
        size_t wtile = ((size_t)(mi >> 1) * nS + s) * 16384 + (size_t)(mi & 1) * 8192;
        const char* wh  = (const char*)Wh + wtile;
        const char* wl  = (const char*)Wl + wtile;
        const char* x0h = (const char*)Xh + ((size_t)t0 * nS + s) * 8192;
        const char* x1h = (const char*)Xh + ((size_t)(t0 + 1) * nS + s) * 8192;
        const char* x0l = (const char*)Xl + ((size_t)t0 * nS + s) * 8192;
        const char* x1l = (const char*)Xl + ((size_t)(t0 + 1) * nS + s) * 8192;
#pragma unroll
        for (int i = 0; i < 12; i++) {
            int c = tid + i * 256;          // 0..3071 16B chunks
            const char* src;
            int doff;
            if (c < 512)       { src = wh + (c * 16);              doff = c * 16; }
            else if (c < 1024) { src = wl + ((c - 512) * 16);      doff = 8192 + (c - 512) * 16; }
            else if (c < 2048) {
                int off = (c - 1024) * 16;
                src = (off < 8192) ? x0h + off : x1h + (off - 8192);
                doff = 16384 + off;
            } else {
                int off = (c - 2048) * 16;
                src = (off < 8192) ? x0l + off : x1l + (off - 8192);
                doff = 32768 + off;
            }
            cp_async16(dst + doff, src);
        }
        cp_commit();
    };

    issue_slab(0, 0);

    for (int s = 0; s < nS; s++) {
        int bi = s & 1;
        if (s + 1 < nS) {
            issue_slab(s + 1, (s + 1) & 1);
            cp_wait<1>();
        } else {
            cp_wait<0>();
        }
        __syncthreads();

        uint32_t bufb = sb + 1024 + (uint32_t)bi * TCB_BYTES;
        uint32_t aH = bufb;
        uint32_t aL = bufb + 8192;
        uint32_t bH = bufb + 16384 + (uint32_t)wn * 8192;
        uint32_t bL = bufb + 32768 + (uint32_t)wn * 8192;

#pragma unroll
        for (int ks = 0; ks < 4; ks++) {
            unsigned ah[4], al[4];
            ldsm_x4(ah, aH + swz128(pA + ks * 32));
            ldsm_x4(al, aL + swz128(pA + ks * 32));
#pragma unroll
            for (int half = 0; half < 2; half++) {
                unsigned bh2[2][4], bl2[2][4];
#pragma unroll
                for (int np2 = 0; np2 < 2; np2++) {
                    int np = half * 2 + np2;
                    uint32_t pB = (uint32_t)((np * 16 + rowB) * 128) + koffB;
                    ldsm_x4(bh2[np2], bH + swz128(pB + ks * 32));
                    ldsm_x4(bl2[np2], bL + swz128(pB + ks * 32));
                }
#pragma unroll
                for (int np2 = 0; np2 < 2; np2++) {
#pragma unroll
                    for (int e = 0; e < 2; e++) {
                        int nt = half * 4 + np2 * 2 + e;
                        const unsigned* bfh = &bh2[np2][e * 2];
                        const unsigned* bfl = &bl2[np2][e * 2];
                        mma_bf16(acc[nt], ah, bfh);
                        mma_bf16(acc[nt], ah, bfl);
                        mma_bf16(acc[nt], al, bfh);
                    }
                }
            }
        }
        __syncthreads();
    }

    int qrow = lane >> 2;
    int qcol = (lane & 3) * 2;

    if (mode == 0) {
        int t = t0 + wn;
        int r0 = wm + qrow;
        int r1 = r0 + 8;
        float bb0 = bias[m0 + r0];
        float bb1 = bias[m0 + r1];
        float* d0 = C + ((size_t)t * M + m0 + r0) * B_;
        float* d1 = C + ((size_t)t * M + m0 + r1) * B_;
#pragma unroll
        for (int nt = 0; nt < 8; nt++) {
            int col = nt * 8 + qcol;
            *(float2*)(d0 + col) = make_float2(acc[nt][0] + bb0, acc[nt][1] + bb0);
            *(float2*)(d1 + col) = make_float2(acc[nt][2] + bb1, acc[nt][3] + bb1);
        }
    } else {
        // stage [m 0..63][n 0..127] stride 132, then transposed write
        float* stage = (float*)(smem + 1024);
        int r0 = wm + qrow;
        int r1 = r0 + 8;
        float bb0 = bias[m0 + r0];
        float bb1 = bias[m0 + r1];
#pragma unroll
        for (int nt = 0; nt < 8; nt++) {
            int col = wn * 64 + nt * 8 + qcol;
            stage[r0 * 132 + col]     = acc[nt][0] + bb0;
            stage[r0 * 132 + col + 1] = acc[nt][1] + bb0;
            stage[r1 * 132 + col]     = acc[nt][2] + bb1;
            stage[r1 * 132 + col + 1] = acc[nt][3] + bb1;
        }
        __syncthreads();
        int n    = tid >> 1;       // 0..127
        int half = tid & 1;
        int tt   = t0 + (n >> 6);
        int b2   = n & 63;
        float* dst = C + ((size_t)b2 * T_ + tt) * M + m0 + half * 32;
#pragma unroll
        for (int q = 0; q < 8; q++) {
            float4 v = make_float4(stage[(half * 32 + q * 4 + 0) * 132 + n],
                                   stage[(half * 32 + q * 4 + 1) * 132 + n],
                                   stage[(half * 32 + q * 4 + 2) * 132 + n],
                                   stage[(half * 32 + q * 4 + 3) * 132 + n]);
            *(float4*)(dst + q * 4) = v;
        }
    }
}

// =========================================================================
// Persistent GRU layer with TENSOR-CORE recurrent matvec (bf16x3).
// (verbatim R10 k_gru8 — proven at 2.5us/step)
// 128 CTAs = 8 batch-groups (8 b) x 16 j-subs (32 j = 96 gate-rows).
// =========================================================================
#define OFF_WL 99840
#define OFF_HH 199680
#define OFF_HL 208000
#define OFF_HG 216640
#define GRU8_SMEM_BYTES 221248

__global__ __launch_bounds__(256) void k_gru8(
    const float* __restrict__ gates,   // [t][g][b], includes b_ih
    const float* __restrict__ Whh,     // [3H][H]
    const float* __restrict__ bhh,     // [3H]
    float* __restrict__ out,           // [t][h][b]
    unsigned short* __restrict__ hbh,  // [2][64][512] bf16-hi bits
    unsigned short* __restrict__ hbl)  // [2][64][512] bf16-lo bits
{
    extern __shared__ __align__(16) char smem[];
    uint32_t sb = smem_u32(smem);

    int tid   = threadIdx.x;
    int w     = tid >> 5;
    int lane  = tid & 31;
    int group = blockIdx.x >> 4;    // 0..7
    int sub   = blockIdx.x & 15;    // 0..15
    int jj    = tid >> 3;           // 0..31
    int bl    = tid & 7;            // 0..7
    int j0    = sub * 32;
    int bg0   = group * 8;
    int j     = j0 + jj;
    int b     = bg0 + bl;
    int gidx  = group * 32;

    // ---- init: Whh slice -> bf16 hi/lo smem, row = jj*3+gate ----
    for (int idx = tid; idx < 96 * 512; idx += 256) {
        int r = idx >> 9;           // 0..95
        int k = idx & 511;
        int gg = r % 3;
        int ww = r / 3;
        float v = Whh[((size_t)(gg * H_ + j0 + ww)) * H_ + k];
        float rem;
        unsigned short hi = bf16hi_bits(v, rem);
        unsigned short lo = bf16_bits(rem);
        *(unsigned short*)(smem + r * 1040 + k * 2)          = hi;
        *(unsigned short*)(smem + OFF_WL + r * 1040 + k * 2) = lo;
    }
    // zero h smem (hh + hl)
    for (int idx = tid; idx < (2 * 8320) / 4; idx += 256)
        *(uint32_t*)(smem + OFF_HH + idx * 4) = 0u;

    float bhr = bhh[j];
    float bhz = bhh[H_ + j];
    float bhn = bhh[2 * H_ + j];
    float hold = 0.f;

    const float* gp = gates + (size_t)j * B_ + b;
    const size_t tstride = (size_t)G_ * B_;
    const size_t goff    = (size_t)H_ * B_;
    float xr = __ldcs(gp);
    float xz = __ldcs(gp + goff);
    float xn = __ldcs(gp + 2 * goff);

    // ldmatrix address patterns (byte offsets, k-chunk added in loop)
    uint32_t paH = sb + (uint32_t)((w * 16 + (lane & 15)) * 1040 + (lane >> 4) * 16);
    uint32_t paL = paH + OFF_WL;
    uint32_t pbH = sb + OFF_HH + (uint32_t)((lane & 7) * 1040 + ((lane >> 3) & 1) * 16);
    uint32_t pbL = pbH + (OFF_HL - OFF_HH);
    float* hg = (float*)(smem + OFF_HG);

    __syncthreads();

    for (int t = 0; t < T_; t++) {
        // ---- tensor-core hg = Ws @ h (warps 0-5) ----
        if (w < 6) {
            float acc[4] = {0.f, 0.f, 0.f, 0.f};
#pragma unroll
            for (int ks = 0; ks < 32; ks++) {
                uint32_t ko = (uint32_t)ks * 32;
                unsigned ah[4], al[4], bh2[2], bl2[2];
                ldsm_x4(ah, paH + ko);
                ldsm_x4(al, paL + ko);
                ldsm_x2(bh2, pbH + ko);
                ldsm_x2(bl2, pbL + ko);
                mma_bf16(acc, ah, bh2);
                mma_bf16(acc, ah, bl2);
                mma_bf16(acc, al, bh2);
            }
            int r0 = w * 16 + (lane >> 2);
            *(float2*)&hg[r0 * 12 + (lane & 3) * 2]       = make_float2(acc[0], acc[1]);
            *(float2*)&hg[(r0 + 8) * 12 + (lane & 3) * 2] = make_float2(acc[2], acc[3]);
        }
        __syncthreads();

        // ---- gate math (all 256 threads, one (j,b) each) ----
        float ar = hg[(jj * 3 + 0) * 12 + bl];
        float az = hg[(jj * 3 + 1) * 12 + bl];
        float an = hg[(jj * 3 + 2) * 12 + bl];

        float r = 1.f / (1.f + expf(-(xr + ar + bhr)));
        float z = 1.f / (1.f + expf(-(xz + az + bhz)));
        float n = tanhf(xn + r * (an + bhn));
        float hnew = (1.f - z) * n + z * hold;
        hold = hnew;

        out[((size_t)t * H_ + j) * B_ + b] = hnew;
        int par = t & 1;
        {
            float rem;
            unsigned short hi = bf16hi_bits(hnew, rem);
            unsigned short lo = bf16_bits(rem);
            hbh[par * 32768 + b * 512 + j] = hi;
            hbl[par * 32768 + b * 512 + j] = lo;
        }

        // prefetch next-step gates (independent of h)
        if (t + 1 < T_) {
            const float* gq = gp + (size_t)(t + 1) * tstride;
            xr = __ldcs(gq);
            xz = __ldcs(gq + goff);
            xn = __ldcs(gq + 2 * goff);
        }

        // ---- per-group release/acquire barrier over 16 CTAs ----
        __syncthreads();
        if (tid == 0) {
            unsigned g = g_gen2[gidx];
            if (atom_add_release(&g_cnt[gidx], 1u) == 15u) {
                g_cnt[gidx] = 0u;
                st_release(&g_gen2[gidx], g + 1u);
            } else {
                while (ld_acquire(&g_gen2[gidx]) == g) { }
            }
        }
        __syncthreads();

        // ---- reload h bf16 hi/lo, verbatim coalesced (no transpose) ----
        {
            int row  = tid >> 5;            // 0..7 (local b)
            int colb = lane * 32;           // byte offset in 1024B row
            const char* srch = (const char*)(hbh + par * 32768 + (bg0 + row) * 512) + colb;
            const char* srcl = (const char*)(hbl + par * 32768 + (bg0 + row) * 512) + colb;
            float4 v0 = __ldcg((const float4*)srch);
            float4 v1 = __ldcg((const float4*)(srch + 16));
            float4 u0 = __ldcg((const float4*)srcl);
            float4 u1 = __ldcg((const float4*)(srcl + 16));
            *(float4*)(smem + OFF_HH + row * 1040 + colb)      = v0;
            *(float4*)(smem + OFF_HH + row * 1040 + colb + 16) = v1;
            *(float4*)(smem + OFF_HL + row * 1040 + colb)      = u0;
            *(float4*)(smem + OFF_HL + row * 1040 + colb + 16) = u1;
        }
        __syncthreads();
    }
}

// =========================================================================
// hidden[l][b][h] = out_l[T-1][h][b]
// =========================================================================
__global__ __launch_bounds__(256) void k_hidden(float* __restrict__ dst) {
    int idx = blockIdx.x * 256 + threadIdx.x;
    int l  = idx >> 15;
    int rem = idx & 32767;
    int bb = rem >> 9;
    int h  = rem & 511;
    const float* src = l ? g_out1 : g_out0;
    dst[idx] = src[((size_t)(T_ - 1) * H_ + h) * B_ + bb];
}

// =========================================================================
extern "C" void kernel_launch(void* const* d_in, const int* in_sizes, int n_in,
                              void* d_out, int out_size) {
    const float* x    = (const float*)d_in[0];
    const float* Wih0 = (const float*)d_in[1];
    const float* Whh0 = (const float*)d_in[2];
    const float* bih0 = (const float*)d_in[3];
    const float* bhh0 = (const float*)d_in[4];
    const float* Wih1 = (const float*)d_in[5];
    const float* Whh1 = (const float*)d_in[6];
    const float* bih1 = (const float*)d_in[7];
    const float* bhh1 = (const float*)d_in[8];
    const float* fcw  = (const float*)d_in[9];
    const float* fcb  = (const float*)d_in[10];
    float* out = (float*)d_out;

    (void)in_sizes; (void)n_in; (void)out_size;

    cudaFuncSetAttribute(k_gru8, cudaFuncAttributeMaxDynamicSharedMemorySize,
                         GRU8_SMEM_BYTES);
    cudaFuncSetAttribute(k_gemm_mma, cudaFuncAttributeMaxDynamicSharedMemorySize,
                         TC_SMEM_TOTAL);

    float *p_gates, *p_out0, *p_out1;
    cudaGetSymbolAddress((void**)&p_gates, g_gates);
    cudaGetSymbolAddress((void**)&p_out0,  g_out0);
    cudaGetSymbolAddress((void**)&p_out1,  g_out1);
    unsigned short *hbh, *hbl;
    cudaGetSymbolAddress((void**)&hbh, g_hbh);
    cudaGetSymbolAddress((void**)&hbl, g_hbl);
    __nv_bfloat16 *w0h, *w0l, *w1h, *w1l, *wfh, *wfl, *x0h, *x0l, *x1h, *x1l;
    cudaGetSymbolAddress((void**)&w0h, g_w0h);
    cudaGetSymbolAddress((void**)&w0l, g_w0l);
    cudaGetSymbolAddress((void**)&w1h, g_w1h);
    cudaGetSymbolAddress((void**)&w1l, g_w1l);
    cudaGetSymbolAddress((void**)&wfh, g_wfh);
    cudaGetSymbolAddress((void**)&wfl, g_wfl);
    cudaGetSymbolAddress((void**)&x0h, g_x0h);
    cudaGetSymbolAddress((void**)&x0l, g_x0l);
    cudaGetSymbolAddress((void**)&x1h, g_x1h);
    cudaGetSymbolAddress((void**)&x1l, g_x1l);

    // operand prep
    k_prep_w<<<dim3(12, 4), 256>>>(Wih0, w0h, w0l, I_);
    k_prep_w<<<dim3(12, 8), 256>>>(Wih1, w1h, w1l, H_);
    k_prep_w<<<dim3(2, 8),  256>>>(fcw,  wfh, wfl, H_);
    k_prep_x<<<dim3(1024, 4), 256>>>(x);

    // layer 0  (M=64 tiles: G_/64 = 24)
    k_gemm_mma<<<dim3(24, 512), 256, TC_SMEM_TOTAL>>>(w0h, w0l, x0h, x0l, bih0, p_gates, 4, G_, 0);
    k_gru8<<<128, 256, GRU8_SMEM_BYTES>>>(p_gates, Whh0, bhh0, p_out0, hbh, hbl);

    // layer 1
    k_prep_h<<<dim3(1024, 8), 256>>>(p_out0, x1h, x1l);
    k_gemm_mma<<<dim3(24, 512), 256, TC_SMEM_TOTAL>>>(w1h, w1l, x1h, x1l, bih1, p_gates, 8, G_, 0);
    k_gru8<<<128, 256, GRU8_SMEM_BYTES>>>(p_gates, Whh1, bhh1, p_out1, hbh, hbl);

    // FC  (O_/64 = 4)
    k_prep_h<<<dim3(1024, 8), 256>>>(p_out1, x1h, x1l);
    k_gemm_mma<<<dim3(4, 512), 256, TC_SMEM_TOTAL>>>(wfh, wfl, x1h, x1l, fcb, out, 8, O_, 1);

    k_hidden<<<256, 256>>>(out + (size_t)B_ * T_ * O_);
}

// round 13
// speedup vs baseline: 1.3753x; 1.0007x over previous
#include <cuda_runtime.h>
#include <cuda_bf16.h>
#include <cstdint>

#define B_ 64
#define T_ 1024
#define I_ 256
#define H_ 512
#define O_ 256
#define G_ 1536   // 3*H

// ======================= scratch (device globals) =======================
__device__ float g_gates[(size_t)T_ * G_ * B_];   // [t][g][b]
__device__ float g_out0[(size_t)T_ * H_ * B_];    // [t][h][b]
__device__ float g_out1[(size_t)T_ * H_ * B_];    // [t][h][b]
__device__ unsigned g_cnt[8 * 32];                 // per-group barrier counters (padded)
__device__ unsigned g_gen2[8 * 32];                // per-group generations (padded)
__device__ unsigned short g_hbh[2 * 64 * 512];     // h bf16-hi, parity double buffer, [b][k]
__device__ unsigned short g_hbl[2 * 64 * 512];     // h bf16-lo

// pre-swizzled bf16 operand tiles (GEMM phase)
__device__ __nv_bfloat16 g_w0h[12 * 4 * 8192], g_w0l[12 * 4 * 8192];
__device__ __nv_bfloat16 g_w1h[12 * 8 * 8192], g_w1l[12 * 8 * 8192];
__device__ __nv_bfloat16 g_wfh[ 2 * 8 * 8192], g_wfl[ 2 * 8 * 8192];
__device__ __nv_bfloat16 g_x0h[(size_t)T_ * 4 * 4096], g_x0l[(size_t)T_ * 4 * 4096];
__device__ __nv_bfloat16 g_x1h[(size_t)T_ * 8 * 4096], g_x1l[(size_t)T_ * 8 * 4096];

// ======================= small helpers =======================
__device__ __forceinline__ void cp_async16(void* smem_dst, const void* gsrc) {
    unsigned s = (unsigned)__cvta_generic_to_shared(smem_dst);
    asm volatile("cp.async.ca.shared.global [%0], [%1], 16;" :: "r"(s), "l"(gsrc));
}
__device__ __forceinline__ void cp_commit() {
    asm volatile("cp.async.commit_group;");
}
template <int N>
__device__ __forceinline__ void cp_wait() {
    asm volatile("cp.async.wait_group %0;" :: "n"(N));
}
__device__ __forceinline__ unsigned atom_add_release(unsigned* p, unsigned v) {
    unsigned old;
    asm volatile("atom.add.release.gpu.global.u32 %0, [%1], %2;"
                 : "=r"(old) : "l"(p), "r"(v) : "memory");
    return old;
}
__device__ __forceinline__ unsigned ld_acquire(const unsigned* p) {
    unsigned v;
    asm volatile("ld.acquire.gpu.global.u32 %0, [%1];" : "=r"(v) : "l"(p) : "memory");
    return v;
}
__device__ __forceinline__ void st_release(unsigned* p, unsigned v) {
    asm volatile("st.release.gpu.global.u32 [%0], %1;" :: "l"(p), "r"(v) : "memory");
}
__device__ __forceinline__ uint32_t smem_u32(const void* p) {
    return (uint32_t)__cvta_generic_to_shared(p);
}
__host__ __device__ __forceinline__ uint32_t swz128(uint32_t o) {
    return o ^ ((o >> 3) & 0x70);
}
__device__ __forceinline__ unsigned short bf16hi_bits(float v, float& rem) {
    __nv_bfloat16 b = __float2bfloat16(v);
    rem = v - __bfloat162float(b);
    return *reinterpret_cast<unsigned short*>(&b);
}
__device__ __forceinline__ unsigned short bf16_bits(float v) {
    __nv_bfloat16 b = __float2bfloat16(v);
    return *reinterpret_cast<unsigned short*>(&b);
}

// ---- mma.sync / ldmatrix (base-target PTX) ----
__device__ __forceinline__ void ldsm_x4(unsigned* r, uint32_t addr) {
    asm volatile("ldmatrix.sync.aligned.m8n8.x4.shared.b16 {%0,%1,%2,%3}, [%4];"
        : "=r"(r[0]), "=r"(r[1]), "=r"(r[2]), "=r"(r[3]) : "r"(addr));
}
__device__ __forceinline__ void ldsm_x2(unsigned* r, uint32_t addr) {
    asm volatile("ldmatrix.sync.aligned.m8n8.x2.shared.b16 {%0,%1}, [%2];"
        : "=r"(r[0]), "=r"(r[1]) : "r"(addr));
}
__device__ __forceinline__ void mma_bf16(float* d, const unsigned* a, const unsigned* b) {
    asm volatile(
        "mma.sync.aligned.m16n8k16.row.col.f32.bf16.bf16.f32 "
        "{%0,%1,%2,%3}, {%4,%5,%6,%7}, {%8,%9}, {%0,%1,%2,%3};"
        : "+f"(d[0]), "+f"(d[1]), "+f"(d[2]), "+f"(d[3])
        : "r"(a[0]), "r"(a[1]), "r"(a[2]), "r"(a[3]), "r"(b[0]), "r"(b[1]));
}

// =========================================================================
// Prep: W [M,K] fp32 -> hi/lo bf16 SW128 tiles [mi][s][128x64]
// =========================================================================
__global__ __launch_bounds__(256) void k_prep_w(
    const float* __restrict__ src, __nv_bfloat16* __restrict__ dh,
    __nv_bfloat16* __restrict__ dl, int K)
{
    int mi = blockIdx.x, s = blockIdx.y, nS = gridDim.y;
    size_t tbase = ((size_t)mi * nS + s) * 16384;
#pragma unroll
    for (int i = 0; i < 8; i++) {
        int it  = threadIdx.x + i * 256;
        int row = it >> 4;
        int q   = it & 15;
        float4 v = *(const float4*)(src + (size_t)(mi * 128 + row) * K + s * 64 + q * 4);
        float r0, r1, r2, r3;
        ushort4 hi, lo;
        hi.x = bf16hi_bits(v.x, r0); hi.y = bf16hi_bits(v.y, r1);
        hi.z = bf16hi_bits(v.z, r2); hi.w = bf16hi_bits(v.w, r3);
        lo.x = bf16_bits(r0); lo.y = bf16_bits(r1);
        lo.z = bf16_bits(r2); lo.w = bf16_bits(r3);
        uint32_t sw = swz128((uint32_t)(row * 128 + q * 8));
        *(ushort4*)((char*)dh + tbase + sw) = hi;
        *(ushort4*)((char*)dl + tbase + sw) = lo;
    }
}

// =========================================================================
// Prep: x[b][t][k] fp32 -> hi/lo bf16 SW128 tiles [t][s][64(b)x64(k)]
// =========================================================================
__global__ __launch_bounds__(256) void k_prep_x(const float* __restrict__ x) {
    int t = blockIdx.x, s = blockIdx.y, nS = gridDim.y;
    size_t tbase = ((size_t)t * nS + s) * 8192;
#pragma unroll
    for (int i = 0; i < 4; i++) {
        int it = threadIdx.x + i * 256;
        int b  = it >> 4;
        int q  = it & 15;
        float4 v = *(const float4*)(x + ((size_t)b * T_ + t) * I_ + s * 64 + q * 4);
        float r0, r1, r2, r3;
        ushort4 hi, lo;
        hi.x = bf16hi_bits(v.x, r0); hi.y = bf16hi_bits(v.y, r1);
        hi.z = bf16hi_bits(v.z, r2); hi.w = bf16hi_bits(v.w, r3);
        lo.x = bf16_bits(r0); lo.y = bf16_bits(r1);
        lo.z = bf16_bits(r2); lo.w = bf16_bits(r3);
        uint32_t sw = swz128((uint32_t)(b * 128 + q * 8));
        *(ushort4*)((char*)g_x0h + tbase + sw) = hi;
        *(ushort4*)((char*)g_x0l + tbase + sw) = lo;
    }
}

// =========================================================================
// Prep: out[t][h][b] fp32 -> hi/lo bf16 SW128 tiles [t][s][64(b)x64(k)]
// =========================================================================
__global__ __launch_bounds__(256) void k_prep_h(
    const float* __restrict__ src, __nv_bfloat16* __restrict__ dh,
    __nv_bfloat16* __restrict__ dl)
{
    __shared__ float sm[64 * 65];
    int t = blockIdx.x, s = blockIdx.y, nS = gridDim.y;
    size_t tbase = ((size_t)t * nS + s) * 8192;
    const float* blk = src + ((size_t)t * H_ + s * 64) * B_;
#pragma unroll
    for (int i = 0; i < 16; i++) {
        int idx = threadIdx.x + i * 256;
        int k = idx >> 6, b = idx & 63;
        sm[k * 65 + b] = blk[idx];
    }
    __syncthreads();
#pragma unroll
    for (int i = 0; i < 4; i++) {
        int it = threadIdx.x + i * 256;
        int b  = it >> 4;
        int q  = it & 15;
        float v0 = sm[(q * 4 + 0) * 65 + b];
        float v1 = sm[(q * 4 + 1) * 65 + b];
        float v2 = sm[(q * 4 + 2) * 65 + b];
        float v3 = sm[(q * 4 + 3) * 65 + b];
        float r0, r1, r2, r3;
        ushort4 hi, lo;
        hi.x = bf16hi_bits(v0, r0); hi.y = bf16hi_bits(v1, r1);
        hi.z = bf16hi_bits(v2, r2); hi.w = bf16hi_bits(v3, r3);
        lo.x = bf16_bits(r0); lo.y = bf16_bits(r1);
        lo.z = bf16_bits(r2); lo.w = bf16_bits(r3);
        uint32_t sw = swz128((uint32_t)(b * 128 + q * 8));
        *(ushort4*)((char*)dh + tbase + sw) = hi;
        *(ushort4*)((char*)dl + tbase + sw) = lo;
    }
}

// =========================================================================
// mma.sync GEMM (R10 proven version: M=128 tiles)
// =========================================================================
#define TCB_BYTES 65536
#define TC_SMEM_TOTAL (1024 + 2 * TCB_BYTES)

__global__ __launch_bounds__(256) void k_gemm_mma(
    const __nv_bfloat16* __restrict__ Wh, const __nv_bfloat16* __restrict__ Wl,
    const __nv_bfloat16* __restrict__ Xh, const __nv_bfloat16* __restrict__ Xl,
    const float* __restrict__ bias, float* __restrict__ C,
    int nS, int M, int mode)
{
    extern __shared__ __align__(16) char smem[];
    uint32_t sb = smem_u32(smem);
    int tid  = threadIdx.x;
    int wid  = tid >> 5;
    int lane = tid & 31;
    int mi   = blockIdx.x;
    int m0   = mi * 128;
    int t0   = blockIdx.y * 2;

    int wm = (wid >> 1) * 32;
    int wn = (wid & 1);

    uint32_t pA = (uint32_t)((wm + (lane & 15)) * 128 + (lane >> 4) * 16);
    uint32_t rowB = (uint32_t)((lane & 7) + ((lane >> 4) & 1) * 8);
    uint32_t koffB = (uint32_t)(((lane >> 3) & 1) * 16);

    float acc[2][8][4];
#pragma unroll
    for (int i = 0; i < 2; i++)
#pragma unroll
        for (int n = 0; n < 8; n++)
#pragma unroll
            for (int c = 0; c < 4; c++) acc[i][n][c] = 0.f;

    auto issue_slab = [&](int s, int bi) {
        char* dst = smem + 1024 + bi * TCB_BYTES;
        const char* wh  = (const char*)Wh + ((size_t)mi * nS + s) * 16384;
        const char* wl  = (const char*)Wl + ((size_t)mi * nS + s) * 16384;
        const char* x0h = (const char*)Xh + ((size_t)t0 * nS + s) * 8192;
        const char* x1h = (const char*)Xh + ((size_t)(t0 + 1) * nS + s) * 8192;
        const char* x0l = (const char*)Xl + ((size_t)t0 * nS + s) * 8192;
        const char* x1l = (const char*)Xl + ((size_t)(t0 + 1) * nS + s) * 8192;
#pragma unroll
        for (int i = 0; i < 16; i++) {
            int c   = tid + i * 256;
            int reg = c >> 10;
            int off = (c & 1023) * 16;
            const char* src;
            if      (reg == 0) src = wh + off;
            else if (reg == 1) src = wl + off;
            else if (reg == 2) src = (off < 8192) ? x0h + off : x1h + (off - 8192);
            else               src = (off < 8192) ? x0l + off : x1l + (off - 8192);
            cp_async16(dst + reg * 16384 + off, src);
        }
        cp_commit();
    };

    issue_slab(0, 0);

    for (int s = 0; s < nS; s++) {
        int bi = s & 1;
        if (s + 1 < nS) {
            issue_slab(s + 1, (s + 1) & 1);
            cp_wait<1>();
        } else {
            cp_wait<0>();
        }
        __syncthreads();

        uint32_t bufb = sb + 1024 + (uint32_t)bi * TCB_BYTES;
        uint32_t aH = bufb;
        uint32_t aL = bufb + 16384;
        uint32_t bH = bufb + 32768 + (uint32_t)wn * 8192;
        uint32_t bL = bufb + 49152 + (uint32_t)wn * 8192;

#pragma unroll
        for (int ks = 0; ks < 4; ks++) {
            unsigned ah[2][4], al[2][4];
            ldsm_x4(ah[0], aH + swz128(pA + ks * 32));
            ldsm_x4(ah[1], aH + swz128(pA + 2048 + ks * 32));
            ldsm_x4(al[0], aL + swz128(pA + ks * 32));
            ldsm_x4(al[1], aL + swz128(pA + 2048 + ks * 32));
#pragma unroll
            for (int half = 0; half < 2; half++) {
                unsigned bh2[2][4], bl2[2][4];
#pragma unroll
                for (int np2 = 0; np2 < 2; np2++) {
                    int np = half * 2 + np2;
                    uint32_t pB = (uint32_t)((np * 16 + rowB) * 128) + koffB;
                    ldsm_x4(bh2[np2], bH + swz128(pB + ks * 32));
                    ldsm_x4(bl2[np2], bL + swz128(pB + ks * 32));
                }
#pragma unroll
                for (int np2 = 0; np2 < 2; np2++) {
#pragma unroll
                    for (int e = 0; e < 2; e++) {
                        int nt = half * 4 + np2 * 2 + e;
                        const unsigned* bfh = &bh2[np2][e * 2];
                        const unsigned* bfl = &bl2[np2][e * 2];
#pragma unroll
                        for (int i = 0; i < 2; i++) {
                            mma_bf16(acc[i][nt], ah[i], bfh);
                            mma_bf16(acc[i][nt], ah[i], bfl);
                            mma_bf16(acc[i][nt], al[i], bfh);
                        }
                    }
                }
            }
        }
        __syncthreads();
    }

    int qrow = lane >> 2;
    int qcol = (lane & 3) * 2;

    if (mode == 0) {
        int t = t0 + wn;
#pragma unroll
        for (int i = 0; i < 2; i++) {
            int r0 = wm + i * 16 + qrow;
            int r1 = r0 + 8;
            float bb0 = bias[m0 + r0];
            float bb1 = bias[m0 + r1];
            float* d0 = C + ((size_t)t * M + m0 + r0) * B_;
            float* d1 = C + ((size_t)t * M + m0 + r1) * B_;
#pragma unroll
            for (int nt = 0; nt < 8; nt++) {
                int col = nt * 8 + qcol;
                *(float2*)(d0 + col) = make_float2(acc[i][nt][0] + bb0, acc[i][nt][1] + bb0);
                *(float2*)(d1 + col) = make_float2(acc[i][nt][2] + bb1, acc[i][nt][3] + bb1);
            }
        }
    } else {
        float* stage = (float*)(smem + 1024);
#pragma unroll
        for (int i = 0; i < 2; i++) {
            int r0 = wm + i * 16 + qrow;
            int r1 = r0 + 8;
            float bb0 = bias[m0 + r0];
            float bb1 = bias[m0 + r1];
#pragma unroll
            for (int nt = 0; nt < 8; nt++) {
                int col = wn * 64 + nt * 8 + qcol;
                stage[r0 * 132 + col]     = acc[i][nt][0] + bb0;
                stage[r0 * 132 + col + 1] = acc[i][nt][1] + bb0;
                stage[r1 * 132 + col]     = acc[i][nt][2] + bb1;
                stage[r1 * 132 + col + 1] = acc[i][nt][3] + bb1;
            }
        }
        __syncthreads();
        int n    = tid >> 1;
        int half = tid & 1;
        int tt   = t0 + (n >> 6);
        int b2   = n & 63;
        float* dst = C + ((size_t)b2 * T_ + tt) * M + m0 + half * 64;
#pragma unroll
        for (int q = 0; q < 16; q++) {
            float4 v = make_float4(stage[(half * 64 + q * 4 + 0) * 132 + n],
                                   stage[(half * 64 + q * 4 + 1) * 132 + n],
                                   stage[(half * 64 + q * 4 + 2) * 132 + n],
                                   stage[(half * 64 + q * 4 + 3) * 132 + n]);
            *(float4*)(dst + q * 4) = v;
        }
    }
}

// =========================================================================
// Persistent GRU layer, tensor-core matvec, BALANCED 8-warp MMA +
// coalesced h publication.
// 128 CTAs = 8 batch-groups (8 b) x 16 j-subs (32 j = 96 gate-rows).
// MMA split: warps 0-3 -> tiles 0-3 full K; tiles 4,5 split K-halves
// across warps {4,6} and {5,7}; second halves land in hgB, summed in
// gate math. h hi/lo published via smem stage -> 16 coalesced wavefronts.
// =========================================================================
#define OFF_WL  99840
#define OFF_HH  199680
#define OFF_HL  208000
#define OFF_HG  216320
#define OFF_HGB 220928
#define OFF_STG 222464
#define GRU10_SMEM_BYTES 223488

__global__ __launch_bounds__(256) void k_gru10(
    const float* __restrict__ gates,   // [t][g][b], includes b_ih
    const float* __restrict__ Whh,     // [3H][H]
    const float* __restrict__ bhh,     // [3H]
    float* __restrict__ out,           // [t][h][b]
    unsigned short* __restrict__ hbh,  // [2][64][512] bf16-hi bits
    unsigned short* __restrict__ hbl)  // [2][64][512] bf16-lo bits
{
    extern __shared__ __align__(16) char smem[];
    uint32_t sb = smem_u32(smem);

    int tid   = threadIdx.x;
    int w     = tid >> 5;
    int lane  = tid & 31;
    int group = blockIdx.x >> 4;    // 0..7
    int sub   = blockIdx.x & 15;    // 0..15
    int jj    = tid >> 3;           // 0..31
    int bl    = tid & 7;            // 0..7
    int j0    = sub * 32;
    int bg0   = group * 8;
    int j     = j0 + jj;
    int b     = bg0 + bl;
    int gidx  = group * 32;

    // warp MMA assignment: balanced across SMSPs
    int mt, ks0;    // tile index, k-start (in 16-elem chunks)
    int kfull;      // 1 if 32 chunks, 0 if 16
    if (w < 4)      { mt = w;     ks0 = 0;  kfull = 1; }
    else if (w < 6) { mt = w;     ks0 = 0;  kfull = 0; }   // tiles 4,5 first half
    else            { mt = w - 2; ks0 = 16; kfull = 0; }   // tiles 4,5 second half

    // ---- init: Whh slice -> bf16 hi/lo smem, row = jj*3+gate ----
    for (int idx = tid; idx < 96 * 512; idx += 256) {
        int r = idx >> 9;
        int k = idx & 511;
        int gg = r % 3;
        int ww = r / 3;
        float v = Whh[((size_t)(gg * H_ + j0 + ww)) * H_ + k];
        float rem;
        unsigned short hi = bf16hi_bits(v, rem);
        unsigned short lo = bf16_bits(rem);
        *(unsigned short*)(smem + r * 1040 + k * 2)          = hi;
        *(unsigned short*)(smem + OFF_WL + r * 1040 + k * 2) = lo;
    }
    // zero h smem (hh + hl)
    for (int idx = tid; idx < (2 * 8320) / 4; idx += 256)
        *(uint32_t*)(smem + OFF_HH + idx * 4) = 0u;

    float bhr = bhh[j];
    float bhz = bhh[H_ + j];
    float bhn = bhh[2 * H_ + j];
    float hold = 0.f;

    const float* gp = gates + (size_t)j * B_ + b;
    const size_t tstride = (size_t)G_ * B_;
    const size_t goff    = (size_t)H_ * B_;
    float xr = __ldcs(gp);
    float xz = __ldcs(gp + goff);
    float xn = __ldcs(gp + 2 * goff);

    // ldmatrix address patterns
    uint32_t paH = sb + (uint32_t)((mt * 16 + (lane & 15)) * 1040 + (lane >> 4) * 16);
    uint32_t paL = paH + OFF_WL;
    uint32_t pbH = sb + OFF_HH + (uint32_t)((lane & 7) * 1040 + ((lane >> 3) & 1) * 16);
    uint32_t pbL = pbH + (OFF_HL - OFF_HH);
    float* hg  = (float*)(smem + OFF_HG);
    float* hgB = (float*)(smem + OFF_HGB);
    unsigned short* sth = (unsigned short*)(smem + OFF_STG);       // [8][32]
    unsigned short* stl = sth + 256;

    __syncthreads();

    for (int t = 0; t < T_; t++) {
        int par = t & 1;

        // ---- tensor-core hg = Ws @ h (all 8 warps, balanced) ----
        {
            float acc[4] = {0.f, 0.f, 0.f, 0.f};
            auto mma_k16 = [&](int kb) {
#pragma unroll
                for (int kk = 0; kk < 16; kk++) {
                    uint32_t ko = (uint32_t)(kb + kk) * 32;
                    unsigned ah[4], al[4], bh2[2], bl2[2];
                    ldsm_x4(ah, paH + ko);
                    ldsm_x4(al, paL + ko);
                    ldsm_x2(bh2, pbH + ko);
                    ldsm_x2(bl2, pbL + ko);
                    mma_bf16(acc, ah, bh2);
                    mma_bf16(acc, ah, bl2);
                    mma_bf16(acc, al, bh2);
                }
            };
            if (kfull) { mma_k16(0); mma_k16(16); }
            else       { mma_k16(ks0); }

            int lr = lane >> 2;
            int cc = (lane & 3) * 2;
            if (w < 6) {
                int r0 = mt * 16 + lr;
                *(float2*)&hg[r0 * 12 + cc]       = make_float2(acc[0], acc[1]);
                *(float2*)&hg[(r0 + 8) * 12 + cc] = make_float2(acc[2], acc[3]);
            } else {
                int r0 = (mt - 4) * 16 + lr;
                *(float2*)&hgB[r0 * 12 + cc]       = make_float2(acc[0], acc[1]);
                *(float2*)&hgB[(r0 + 8) * 12 + cc] = make_float2(acc[2], acc[3]);
            }
        }
        __syncthreads();

        // ---- gate math (all 256 threads, one (j,b) each) ----
        int r0 = jj * 3;
        float ar = hg[(r0 + 0) * 12 + bl];
        float az = hg[(r0 + 1) * 12 + bl];
        float an = hg[(r0 + 2) * 12 + bl];
        if (r0 + 0 >= 64) ar += hgB[(r0 - 64) * 12 + bl];
        if (r0 + 1 >= 64) az += hgB[(r0 - 63) * 12 + bl];
        if (r0 + 2 >= 64) an += hgB[(r0 - 62) * 12 + bl];

        float r = 1.f / (1.f + expf(-(xr + ar + bhr)));
        float z = 1.f / (1.f + expf(-(xz + az + bhz)));
        float n = tanhf(xn + r * (an + bhn));
        float hnew = (1.f - z) * n + z * hold;
        hold = hnew;

        out[((size_t)t * H_ + j) * B_ + b] = hnew;
        {
            float rem;
            sth[bl * 32 + jj] = bf16hi_bits(hnew, rem);
            stl[bl * 32 + jj] = bf16_bits(rem);
        }

        // prefetch next-step gates (independent of h)
        if (t + 1 < T_) {
            const float* gq = gp + (size_t)(t + 1) * tstride;
            xr = __ldcs(gq);
            xz = __ldcs(gq + goff);
            xn = __ldcs(gq + 2 * goff);
        }

        __syncthreads();   // stage ready

        // ---- coalesced h publication: 64 threads, 16B each ----
        if (tid < 64) {
            int isLo = tid >> 5;
            int c    = tid & 31;
            int row  = c >> 2;
            int o16  = c & 3;
            const char* s = (const char*)(isLo ? stl : sth) + row * 64 + o16 * 16;
            float4 v = *(const float4*)s;
            unsigned short* dstb = isLo ? hbl : hbh;
            char* d = (char*)(dstb + par * 32768 + (size_t)(bg0 + row) * 512 + j0) + o16 * 16;
            *(float4*)d = v;
        }
        __syncthreads();   // STGs issued before arrive

        // ---- per-group release/acquire barrier over 16 CTAs ----
        if (tid == 0) {
            unsigned g = g_gen2[gidx];
            if (atom_add_release(&g_cnt[gidx], 1u) == 15u) {
                g_cnt[gidx] = 0u;
                st_release(&g_gen2[gidx], g + 1u);
            } else {
                while (ld_acquire(&g_gen2[gidx]) == g) { }
            }
        }
        __syncthreads();

        // ---- reload h bf16 hi/lo, coalesced (no transpose) ----
        {
            int row  = tid >> 5;            // 0..7 (local b)
            int colb = lane * 32;           // byte offset in 1024B row
            const char* srch = (const char*)(hbh + par * 32768 + (size_t)(bg0 + row) * 512) + colb;
            const char* srcl = (const char*)(hbl + par * 32768 + (size_t)(bg0 + row) * 512) + colb;
            float4 v0 = __ldcg((const float4*)srch);
            float4 v1 = __ldcg((const float4*)(srch + 16));
            float4 u0 = __ldcg((const float4*)srcl);
            float4 u1 = __ldcg((const float4*)(srcl + 16));
            *(float4*)(smem + OFF_HH + row * 1040 + colb)      = v0;
            *(float4*)(smem + OFF_HH + row * 1040 + colb + 16) = v1;
            *(float4*)(smem + OFF_HL + row * 1040 + colb)      = u0;
            *(float4*)(smem + OFF_HL + row * 1040 + colb + 16) = u1;
        }
        __syncthreads();
    }
}

// =========================================================================
// hidden[l][b][h] = out_l[T-1][h][b]
// =========================================================================
__global__ __launch_bounds__(256) void k_hidden(float* __restrict__ dst) {
    int idx = blockIdx.x * 256 + threadIdx.x;
    int l  = idx >> 15;
    int rem = idx & 32767;
    int bb = rem >> 9;
    int h  = rem & 511;
    const float* src = l ? g_out1 : g_out0;
    dst[idx] = src[((size_t)(T_ - 1) * H_ + h) * B_ + bb];
}

// =========================================================================
extern "C" void kernel_launch(void* const* d_in, const int* in_sizes, int n_in,
                              void* d_out, int out_size) {
    const float* x    = (const float*)d_in[0];
    const float* Wih0 = (const float*)d_in[1];
    const float* Whh0 = (const float*)d_in[2];
    const float* bih0 = (const float*)d_in[3];
    const float* bhh0 = (const float*)d_in[4];
    const float* Wih1 = (const float*)d_in[5];
    const float* Whh1 = (const float*)d_in[6];
    const float* bih1 = (const float*)d_in[7];
    const float* bhh1 = (const float*)d_in[8];
    const float* fcw  = (const float*)d_in[9];
    const float* fcb  = (const float*)d_in[10];
    float* out = (float*)d_out;

    (void)in_sizes; (void)n_in; (void)out_size;

    cudaFuncSetAttribute(k_gru10, cudaFuncAttributeMaxDynamicSharedMemorySize,
                         GRU10_SMEM_BYTES);
    cudaFuncSetAttribute(k_gemm_mma, cudaFuncAttributeMaxDynamicSharedMemorySize,
                         TC_SMEM_TOTAL);

    float *p_gates, *p_out0, *p_out1;
    cudaGetSymbolAddress((void**)&p_gates, g_gates);
    cudaGetSymbolAddress((void**)&p_out0,  g_out0);
    cudaGetSymbolAddress((void**)&p_out1,  g_out1);
    unsigned short *hbh, *hbl;
    cudaGetSymbolAddress((void**)&hbh, g_hbh);
    cudaGetSymbolAddress((void**)&hbl, g_hbl);
    __nv_bfloat16 *w0h, *w0l, *w1h, *w1l, *wfh, *wfl, *x0h, *x0l, *x1h, *x1l;
    cudaGetSymbolAddress((void**)&w0h, g_w0h);
    cudaGetSymbolAddress((void**)&w0l, g_w0l);
    cudaGetSymbolAddress((void**)&w1h, g_w1h);
    cudaGetSymbolAddress((void**)&w1l, g_w1l);
    cudaGetSymbolAddress((void**)&wfh, g_wfh);
    cudaGetSymbolAddress((void**)&wfl, g_wfl);
    cudaGetSymbolAddress((void**)&x0h, g_x0h);
    cudaGetSymbolAddress((void**)&x0l, g_x0l);
    cudaGetSymbolAddress((void**)&x1h, g_x1h);
    cudaGetSymbolAddress((void**)&x1l, g_x1l);

    // operand prep
    k_prep_w<<<dim3(12, 4), 256>>>(Wih0, w0h, w0l, I_);
    k_prep_w<<<dim3(12, 8), 256>>>(Wih1, w1h, w1l, H_);
    k_prep_w<<<dim3(2, 8),  256>>>(fcw,  wfh, wfl, H_);
    k_prep_x<<<dim3(1024, 4), 256>>>(x);

    // layer 0
    k_gemm_mma<<<dim3(12, 512), 256, TC_SMEM_TOTAL>>>(w0h, w0l, x0h, x0l, bih0, p_gates, 4, G_, 0);
    k_gru10<<<128, 256, GRU10_SMEM_BYTES>>>(p_gates, Whh0, bhh0, p_out0, hbh, hbl);

    // layer 1
    k_prep_h<<<dim3(1024, 8), 256>>>(p_out0, x1h, x1l);
    k_gemm_mma<<<dim3(12, 512), 256, TC_SMEM_TOTAL>>>(w1h, w1l, x1h, x1l, bih1, p_gates, 8, G_, 0);
    k_gru10<<<128, 256, GRU10_SMEM_BYTES>>>(p_gates, Whh1, bhh1, p_out1, hbh, hbl);

    // FC
    k_prep_h<<<dim3(1024, 8), 256>>>(p_out1, x1h, x1l);
    k_gemm_mma<<<dim3(2, 512), 256, TC_SMEM_TOTAL>>>(wfh, wfl, x1h, x1l, fcb, out, 8, O_, 1);

    k_hidden<<<256, 256>>>(out + (size_t)B_ * T_ * O_);
}